// round 11
// baseline (speedup 1.0000x reference)
#include <cuda_runtime.h>
#include <cuda_fp16.h>
#include <cstdint>

// Problem constants
#define TOK  4096
#define DIM  1024
#define NE   8
#define DFFC 4096

#define BM   128
#define BK   32
#define CAP  9216
#define MT   (CAP/BM)
#define HSTR 40            // halfs per smem row (64B data + 16B pad), ldmatrix conflict-free
#define NCHUNK 2           // wconv13 / gemm13 / gemm2-K pipeline chunks over DFF

// ---------------- device scratch ----------------
__device__ int    g_off[NE];
__device__ int    g_rows[NE];
__device__ int    g_fill[NE];
__device__ int    g_eid[TOK*2];
__device__ float  g_ew[TOK*2];
__device__ int    g_perm[CAP];
__device__ float  g_pw[CAP];
__device__ __half g_X[(size_t)CAP*DIM];     // gathered fp16 activations (pads = 0)
__device__ __half g_H[(size_t)CAP*DFFC];    // fp16 hidden activations
__device__ __half g_W1h[(size_t)NE*DFFC*DIM];
__device__ __half g_W3h[(size_t)NE*DFFC*DIM];
__device__ __half g_W2h[(size_t)NE*DIM*DFFC];

// ---------------- PTX helpers ----------------
__device__ __forceinline__ uint32_t smem_u32(const void* p) {
    uint32_t a;
    asm("{ .reg .u64 t; cvta.to.shared.u64 t, %1; cvt.u32.u64 %0, t; }" : "=r"(a) : "l"(p));
    return a;
}

#define CPA(s, g)   asm volatile("cp.async.cg.shared.global [%0], [%1], 16;" :: "r"(s), "l"(g) : "memory")
#define CPCOMMIT()  asm volatile("cp.async.commit_group;" ::: "memory")
#define CPWAIT(n)   asm volatile("cp.async.wait_group %0;" :: "n"(n) : "memory")

#define LDSM4(r, a) asm volatile("ldmatrix.sync.aligned.m8n8.x4.shared.b16 {%0,%1,%2,%3}, [%4];" \
    : "=r"((r)[0]), "=r"((r)[1]), "=r"((r)[2]), "=r"((r)[3]) : "r"(a))

// c += a*b   (m16n8k16 fp16 in, fp32 accumulate)
#define MMAH(c, a, b0, b1) asm volatile( \
    "mma.sync.aligned.m16n8k16.row.col.f32.f16.f16.f32 " \
    "{%0,%1,%2,%3},{%4,%5,%6,%7},{%8,%9},{%0,%1,%2,%3};" \
    : "+f"((c)[0]), "+f"((c)[1]), "+f"((c)[2]), "+f"((c)[3]) \
    : "r"((a)[0]), "r"((a)[1]), "r"((a)[2]), "r"((a)[3]), "r"(b0), "r"(b1))

// ---------------- setup kernels ----------------
// One warp per token, float4 loads (Wg rows stay hot in L1/L2).
__global__ void k_router(const float* __restrict__ x,
                         const float* __restrict__ Wg,
                         const float* __restrict__ bg) {
    int warp = threadIdx.x >> 5, lane = threadIdx.x & 31;
    int t = blockIdx.x * 4 + warp;
    const float4* xr = reinterpret_cast<const float4*>(x + (size_t)t * DIM);
    const float4* wg = reinterpret_cast<const float4*>(Wg);
    float acc[NE];
#pragma unroll
    for (int e = 0; e < NE; e++) acc[e] = 0.f;
#pragma unroll
    for (int k = 0; k < 8; k++) {
        float4 xv = xr[lane + k * 32];
#pragma unroll
        for (int e = 0; e < NE; e++) {
            float4 w = wg[e * 256 + lane + k * 32];
            acc[e] += xv.x * w.x + xv.y * w.y + xv.z * w.z + xv.w * w.w;
        }
    }
#pragma unroll
    for (int e = 0; e < NE; e++)
#pragma unroll
        for (int o = 16; o > 0; o >>= 1)
            acc[e] += __shfl_xor_sync(0xffffffffu, acc[e], o);
    if (lane == 0) {
        float v0 = -1e30f, v1 = -1e30f; int i0 = 0, i1 = 0;
#pragma unroll
        for (int e = 0; e < NE; e++) {
            float v = acc[e] + bg[e];
            if (v > v0)      { v1 = v0; i1 = i0; v0 = v; i0 = e; }
            else if (v > v1) { v1 = v;  i1 = e; }
        }
        float e1 = __expf(v1 - v0);
        float w0 = 1.f / (1.f + e1);
        float w1 = e1 * w0;
        g_eid[2*t] = i0; g_eid[2*t+1] = i1;
        g_ew [2*t] = w0; g_ew [2*t+1] = w1;
    }
}

// histogram + offsets + fill reset, single block
__global__ void k_count() {
    __shared__ int cnt[NE];
    int tid = threadIdx.x;
    if (tid < NE) cnt[tid] = 0;
    __syncthreads();
    for (int i = tid; i < TOK * 2; i += 256) atomicAdd(&cnt[g_eid[i]], 1);
    __syncthreads();
    if (tid == 0) {
        int acc = 0;
        for (int e = 0; e < NE; e++) {
            g_off[e]  = acc;
            g_rows[e] = cnt[e];
            g_fill[e] = 0;
            acc += ((cnt[e] + BM - 1) / BM) * BM;
        }
    }
}

__global__ void k_scatter() {
    int t = blockIdx.x * blockDim.x + threadIdx.x;
    if (t >= TOK) return;
#pragma unroll
    for (int s = 0; s < 2; s++) {
        int e = g_eid[2*t + s];
        int pos = g_off[e] + atomicAdd(&g_fill[e], 1);
        g_perm[pos] = t;
        g_pw[pos]   = g_ew[2*t + s];
    }
}

// Gather tokens into per-expert buckets as fp16 (RN); zero the pad rows. MLP=2.
__global__ void k_gather(const float* __restrict__ x) {
    int pos = blockIdx.x;
    bool valid = false;
#pragma unroll
    for (int e = 0; e < NE; e++)
        valid |= (pos >= g_off[e] && pos < g_off[e] + g_rows[e]);
    int c = threadIdx.x;   // 0..127
    float4 v0 = make_float4(0.f,0.f,0.f,0.f), v1 = v0;
    if (valid) {
        int t = g_perm[pos];
        const float4* src = reinterpret_cast<const float4*>(x + (size_t)t * DIM);
        v0 = src[c];
        v1 = src[c + 128];
    }
    __half2* dst = reinterpret_cast<__half2*>(g_X + (size_t)pos * DIM);
    dst[2*c]           = __floats2half2_rn(v0.x, v0.y);
    dst[2*c + 1]       = __floats2half2_rn(v0.z, v0.w);
    dst[2*(c+128)]     = __floats2half2_rn(v1.x, v1.y);
    dst[2*(c+128) + 1] = __floats2half2_rn(v1.z, v1.w);
}

// fp32 -> fp16 conversion of one DFF-chunk of W1 and W3 (all experts).
__global__ void k_wconv13c(const float4* __restrict__ s1, const float4* __restrict__ s3,
                           __half2* __restrict__ d1, __half2* __restrict__ d3, int chunk) {
    int e = blockIdx.y;
    size_t base = ((size_t)e * DFFC + (size_t)chunk * (DFFC / NCHUNK)) * DIM / 4;
    size_t i = base + blockIdx.x * 256 + threadIdx.x;
    float4 v = s1[i];
    d1[2*i]   = __floats2half2_rn(v.x, v.y);
    d1[2*i+1] = __floats2half2_rn(v.z, v.w);
    float4 w = s3[i];
    d3[2*i]   = __floats2half2_rn(w.x, w.y);
    d3[2*i+1] = __floats2half2_rn(w.z, w.w);
}

__global__ void k_wconv(const float4* __restrict__ src, __half2* __restrict__ dst, int n4) {
    int i = blockIdx.x * blockDim.x + threadIdx.x;
    if (i >= n4) return;
    float4 v = src[i];
    dst[2*i]   = __floats2half2_rn(v.x, v.y);
    dst[2*i+1] = __floats2half2_rn(v.z, v.w);
}

__global__ void k_zero(float4* __restrict__ y) {
    y[blockIdx.x * 256 + threadIdx.x] = make_float4(0.f, 0.f, 0.f, 0.f);
}

__device__ __forceinline__ bool find_expert(int mt, int& e, int& m0, int& ne) {
    e = -1;
#pragma unroll
    for (int i = 0; i < NE; i++) {
        int o = g_off[i], r = g_rows[i];
        int t0 = o / BM, tl = (r + BM - 1) / BM;
        if (mt >= t0 && mt < t0 + tl) { e = i; m0 = o + (mt - t0) * BM; ne = o + r; }
    }
    return e >= 0;
}

// =============== GEMM 1+3 fused: H = silu(X@W1^T)*(X@W3^T), fp16 mma ===============
// CTA tile 128x64 (dual matrices), BK=32, 3-stage cp.async, 8 warps (2m x 4n).
// dyn smem halfs: A 3x(128*40) @0; B1 3x(64*40) @30720B; B3 @46080B. Total 61440B.
__global__ void __launch_bounds__(256, 2)
k_gemm13(int nbase) {
    extern __shared__ __half sm13[];
    const uint32_t sbu = smem_u32(sm13);

    int e, m0, ne_;
    if (!find_expert((int)blockIdx.x, e, m0, ne_)) return;

    const int tid = threadIdx.x, lane = tid & 31, wid = tid >> 5;
    const int wm = wid & 1, wn = wid >> 1;
    const int n0 = nbase + blockIdx.y * 64;

    const __half* Ah  = g_X  + (size_t)m0 * DIM;
    const __half* B1h = g_W1h + ((size_t)e * DFFC + n0) * DIM;
    const __half* B3h = g_W3h + ((size_t)e * DFFC + n0) * DIM;

#define G13_LOAD(s, k0) do {                                                    \
    _Pragma("unroll")                                                           \
    for (int l = 0; l < 2; l++) {                                               \
        int idx = tid + l * 256, row = idx >> 2, q = idx & 3;                   \
        CPA(sbu + (uint32_t)((s)*10240 + row*80 + q*16),                        \
            Ah + (size_t)row * DIM + (k0) + q * 8);                             \
    }                                                                           \
    { int row = tid >> 2, q = tid & 3;                                          \
      CPA(sbu + (uint32_t)(30720 + (s)*5120 + row*80 + q*16),                   \
          B1h + (size_t)row * DIM + (k0) + q * 8);                              \
      CPA(sbu + (uint32_t)(46080 + (s)*5120 + row*80 + q*16),                   \
          B3h + (size_t)row * DIM + (k0) + q * 8); }                            \
    CPCOMMIT();                                                                 \
} while (0)

    const uint32_t aBase = sbu +
        (uint32_t)(((wm*64 + (lane & 15)) * HSTR + (lane >> 4) * 8) * 2);
    const uint32_t bRow = (uint32_t)(wn*16 + (lane & 7) + ((lane >> 4) & 1) * 8);
    const uint32_t bCol = (uint32_t)(((lane >> 3) & 1) * 8);
    const uint32_t b1Base = sbu + 30720u + (bRow * HSTR + bCol) * 2;
    const uint32_t b3Base = b1Base + 15360u;

    float c1[4][2][4], c3[4][2][4];
#pragma unroll
    for (int i = 0; i < 4; i++)
#pragma unroll
        for (int j = 0; j < 2; j++)
#pragma unroll
            for (int q = 0; q < 4; q++) { c1[i][j][q] = 0.f; c3[i][j][q] = 0.f; }

    const int NS = DIM / BK;   // 32
    G13_LOAD(0, 0);
    G13_LOAD(1, BK);

    for (int i = 0; i < NS; i++) {
        int s = i % 3;
        if (i + 1 < NS) CPWAIT(1); else CPWAIT(0);
        __syncthreads();
        if (i + 2 < NS) G13_LOAD((i + 2) % 3, (i + 2) * BK);

        uint32_t b1f[2][4], b3f[2][4];
#pragma unroll
        for (int ks = 0; ks < 2; ks++) {
            LDSM4(b1f[ks], b1Base + (uint32_t)(s*5120 + ks*32));
            LDSM4(b3f[ks], b3Base + (uint32_t)(s*5120 + ks*32));
        }
#pragma unroll
        for (int ks = 0; ks < 2; ks++) {
#pragma unroll
            for (int mt = 0; mt < 4; mt++) {
                uint32_t a[4];
                LDSM4(a, aBase + (uint32_t)(s*10240 + mt*1280 + ks*32));
                MMAH(c1[mt][0], a, b1f[ks][0], b1f[ks][1]);
                MMAH(c1[mt][1], a, b1f[ks][2], b1f[ks][3]);
                MMAH(c3[mt][0], a, b3f[ks][0], b3f[ks][1]);
                MMAH(c3[mt][1], a, b3f[ks][2], b3f[ks][3]);
            }
        }
    }

    // epilogue: h = silu(c1) * c3 -> fp16 -> g_H (pad rows compute exact 0)
#pragma unroll
    for (int mt = 0; mt < 4; mt++)
#pragma unroll
        for (int nj = 0; nj < 2; nj++) {
            int row = m0 + wm*64 + mt*16 + (lane >> 2);
            int col = n0 + wn*16 + nj*8 + (lane & 3) * 2;
#pragma unroll
            for (int h = 0; h < 2; h++) {
                int r = row + h * 8;
                float z0 = c1[mt][nj][h*2],   g0 = z0 / (1.f + __expf(-z0)) * c3[mt][nj][h*2];
                float z1 = c1[mt][nj][h*2+1], g1 = z1 / (1.f + __expf(-z1)) * c3[mt][nj][h*2+1];
                *reinterpret_cast<__half2*>(g_H + (size_t)r * DFFC + col) =
                    __floats2half2_rn(g0, g1);
            }
        }
}

// =============== GEMM 2 (K-chunked): y += w * (H[:,kb:kb+2048] @ W2[:,kb:kb+2048]^T) ===============
// CTA tile 128x128, BK=32, 3-stage, 8 warps (2m x 4n), warp tile 64x32.
// dyn smem halfs: A 3x(128*40) @0; B 3x(128*40) @30720B. Total 61440B.
// Contributions from the 2 K-chunks combine via commutative fp32 atomicAdd.
__global__ void __launch_bounds__(256, 2)
k_gemm2(float* __restrict__ y, int kbase) {
    extern __shared__ __half sm2[];
    const uint32_t sbu = smem_u32(sm2);
    __shared__ int   srow[BM];
    __shared__ float swt[BM];

    int e, m0, ne_;
    if (!find_expert((int)blockIdx.y, e, m0, ne_)) return;

    const int tid = threadIdx.x, lane = tid & 31, wid = tid >> 5;
    const int wm = wid & 1, wn = wid >> 1;
    const int n0 = blockIdx.x * 128;

    if (tid < BM) {
        int pos = m0 + tid;
        bool v = pos < ne_;
        srow[tid] = v ? g_perm[pos] : -1;
        swt[tid]  = v ? g_pw[pos]   : 0.f;
    }

    const __half* Ah = g_H + (size_t)m0 * DFFC + kbase;
    const __half* Bh = g_W2h + ((size_t)e * DIM + n0) * DFFC + kbase;

#define G2_LOAD(s, k0) do {                                                     \
    _Pragma("unroll")                                                           \
    for (int l = 0; l < 2; l++) {                                               \
        int idx = tid + l * 256, row = idx >> 2, q = idx & 3;                   \
        CPA(sbu + (uint32_t)((s)*10240 + row*80 + q*16),                        \
            Ah + (size_t)row * DFFC + (k0) + q * 8);                            \
        CPA(sbu + (uint32_t)(30720 + (s)*10240 + row*80 + q*16),                \
            Bh + (size_t)row * DFFC + (k0) + q * 8);                            \
    }                                                                           \
    CPCOMMIT();                                                                 \
} while (0)

    const uint32_t aBase = sbu +
        (uint32_t)(((wm*64 + (lane & 15)) * HSTR + (lane >> 4) * 8) * 2);
    const uint32_t bRow = (uint32_t)(wn*32 + (lane & 7) + ((lane >> 4) & 1) * 8);
    const uint32_t bCol = (uint32_t)(((lane >> 3) & 1) * 8);
    const uint32_t bBase = sbu + 30720u + (bRow * HSTR + bCol) * 2;

    float c[4][4][4];
#pragma unroll
    for (int i = 0; i < 4; i++)
#pragma unroll
        for (int j = 0; j < 4; j++)
#pragma unroll
            for (int q = 0; q < 4; q++) c[i][j][q] = 0.f;

    const int NS = (DFFC / NCHUNK) / BK;   // 64
    G2_LOAD(0, 0);
    G2_LOAD(1, BK);

    for (int i = 0; i < NS; i++) {
        int s = i % 3;
        if (i + 1 < NS) CPWAIT(1); else CPWAIT(0);
        __syncthreads();
        if (i + 2 < NS) G2_LOAD((i + 2) % 3, (i + 2) * BK);

        uint32_t bf[2][2][4];   // [nt][ks]
#pragma unroll
        for (int nt = 0; nt < 2; nt++)
#pragma unroll
            for (int ks = 0; ks < 2; ks++)
                LDSM4(bf[nt][ks], bBase + (uint32_t)(s*10240 + nt*1280 + ks*32));
#pragma unroll
        for (int ks = 0; ks < 2; ks++) {
#pragma unroll
            for (int mt = 0; mt < 4; mt++) {
                uint32_t a[4];
                LDSM4(a, aBase + (uint32_t)(s*10240 + mt*1280 + ks*32));
#pragma unroll
                for (int nt = 0; nt < 2; nt++) {
                    MMAH(c[mt][nt*2],   a, bf[nt][ks][0], bf[nt][ks][1]);
                    MMAH(c[mt][nt*2+1], a, bf[nt][ks][2], bf[nt][ks][3]);
                }
            }
        }
    }

    // epilogue: weighted scatter-add (commutative fp32 adds per output element)
#pragma unroll
    for (int mt = 0; mt < 4; mt++) {
        int rl = wm*64 + mt*16 + (lane >> 2);
#pragma unroll
        for (int h = 0; h < 2; h++) {
            int r = rl + h * 8;
            int t = srow[r];
            if (t >= 0) {
                float w = swt[r];
                float* yr = y + (size_t)t * DIM + n0 + wn*32 + (lane & 3) * 2;
#pragma unroll
                for (int nj = 0; nj < 4; nj++) {
                    atomicAdd(&yr[nj*8],     w * c[mt][nj][h*2]);
                    atomicAdd(&yr[nj*8 + 1], w * c[mt][nj][h*2+1]);
                }
            }
        }
    }
}

// ---------------- launch ----------------
#define SMEM_GEMM 61440

extern "C" void kernel_launch(void* const* d_in, const int* in_sizes, int n_in,
                              void* d_out, int out_size) {
    const float* x  = (const float*)d_in[0];
    const float* Wg = (const float*)d_in[1];
    const float* bg = (const float*)d_in[2];
    const float* W1 = (const float*)d_in[3];
    const float* W2 = (const float*)d_in[4];
    const float* W3 = (const float*)d_in[5];
    float* y = (float*)d_out;

    // One-time infra: exactly ONE extra stream + 5 tiny events (same footprint
    // as the passing R7/R10 runs). First call is the non-captured correctness run.
    static cudaStream_t s2 = nullptr;
    static cudaEvent_t evFork, evC0, evGather, evTail, evG1;
    if (s2 == nullptr) {
        cudaStreamCreateWithFlags(&s2, cudaStreamNonBlocking);
        cudaEventCreateWithFlags(&evFork,   cudaEventDisableTiming);
        cudaEventCreateWithFlags(&evC0,     cudaEventDisableTiming);
        cudaEventCreateWithFlags(&evGather, cudaEventDisableTiming);
        cudaEventCreateWithFlags(&evTail,   cudaEventDisableTiming);
        cudaEventCreateWithFlags(&evG1,     cudaEventDisableTiming);
        cudaFuncSetAttribute(k_gemm13, cudaFuncAttributeMaxDynamicSharedMemorySize, SMEM_GEMM);
        cudaFuncSetAttribute(k_gemm2,  cudaFuncAttributeMaxDynamicSharedMemorySize, SMEM_GEMM);
    }

    __half* w1h; cudaGetSymbolAddress((void**)&w1h, g_W1h);
    __half* w3h; cudaGetSymbolAddress((void**)&w3h, g_W3h);
    __half* w2h; cudaGetSymbolAddress((void**)&w2h, g_W2h);
    const int NW = NE * DFFC * DIM / 4;   // float4 count per weight tensor

    // Side stream s2: W1/W3 chunk conversions, W2 conversion, y zeroing,
    // then gemm13 chunk 1 (back-fills into chunk 0's tail).
    cudaEventRecord(evFork, 0);
    cudaStreamWaitEvent(s2, evFork, 0);
    dim3 gwc((DFFC / NCHUNK) * DIM / 4 / 256, NE);   // (2048, 8)
    k_wconv13c<<<gwc, 256, 0, s2>>>((const float4*)W1, (const float4*)W3,
                                    (__half2*)w1h, (__half2*)w3h, 0);
    cudaEventRecord(evC0, s2);
    k_wconv13c<<<gwc, 256, 0, s2>>>((const float4*)W1, (const float4*)W3,
                                    (__half2*)w1h, (__half2*)w3h, 1);
    k_wconv<<<(NW + 255) / 256, 256, 0, s2>>>((const float4*)W2, (__half2*)w2h, NW);
    k_zero<<<(TOK * DIM) / 1024, 256, 0, s2>>>((float4*)y);
    cudaEventRecord(evTail, s2);                     // W2h + y ready

    // Main stream: routing chain (overlaps with chunk-0 weight conversion).
    k_router<<<TOK / 4, 128>>>(x, Wg, bg);
    k_count<<<1, 256>>>();
    k_scatter<<<TOK / 256, 256>>>();
    k_gather<<<CAP, 128>>>(x);
    cudaEventRecord(evGather, 0);

    dim3 g13(MT, (DFFC / NCHUNK) / 64);   // (72, 32)
    // gemm13 chunk 0 on main: gated by gather (program order) + its weights.
    cudaStreamWaitEvent(0, evC0, 0);
    k_gemm13<<<g13, 256, SMEM_GEMM>>>(0);
    // gemm13 chunk 1 on s2 (weights ready by s2 program order; needs gather).
    cudaStreamWaitEvent(s2, evGather, 0);
    k_gemm13<<<g13, 256, SMEM_GEMM, s2>>>(DFFC / NCHUNK);
    cudaEventRecord(evG1, s2);

    // gemm2 K-chunk 0 on main right after gemm13 c0 (needs only H[:,0:2048]);
    // it back-fills gemm13 c1's tail on s2. Requires W2h + zeroed y (evTail).
    dim3 g2(DIM / 128, MT);            // x = n (8): g_H tile L2 reuse
    cudaStreamWaitEvent(0, evTail, 0);
    k_gemm2<<<g2, 256, SMEM_GEMM>>>(y, 0);

    // gemm2 K-chunk 1 after gemm13 c1 completes.
    cudaStreamWaitEvent(0, evG1, 0);
    k_gemm2<<<g2, 256, SMEM_GEMM>>>(y, DFFC / NCHUNK);
}

// round 12
// speedup vs baseline: 1.5354x; 1.5354x over previous
#include <cuda_runtime.h>
#include <cuda_fp16.h>
#include <cstdint>

// Problem constants
#define TOK  4096
#define DIM  1024
#define NE   8
#define DFFC 4096

#define BM   128
#define BK   32
#define CAP  9216
#define MT   (CAP/BM)
#define HSTR 40            // halfs per smem row (64B data + 16B pad), ldmatrix conflict-free
#define NCHUNK 2           // wconv13 / gemm13 pipeline chunks over DFF

// ---------------- device scratch ----------------
__device__ int    g_off[NE];
__device__ int    g_rows[NE];
__device__ int    g_fill[NE];
__device__ int    g_eid[TOK*2];
__device__ float  g_ew[TOK*2];
__device__ int    g_perm[CAP];
__device__ float  g_pw[CAP];
__device__ __half g_X[(size_t)CAP*DIM];     // gathered fp16 activations (pads = 0)
__device__ __half g_H[(size_t)CAP*DFFC];    // fp16 hidden activations
__device__ __half g_W1h[(size_t)NE*DFFC*DIM];
__device__ __half g_W3h[(size_t)NE*DFFC*DIM];
__device__ __half g_W2h[(size_t)NE*DIM*DFFC];

// ---------------- PTX helpers ----------------
__device__ __forceinline__ uint32_t smem_u32(const void* p) {
    uint32_t a;
    asm("{ .reg .u64 t; cvta.to.shared.u64 t, %1; cvt.u32.u64 %0, t; }" : "=r"(a) : "l"(p));
    return a;
}

#define CPA(s, g)   asm volatile("cp.async.cg.shared.global [%0], [%1], 16;" :: "r"(s), "l"(g) : "memory")
#define CPCOMMIT()  asm volatile("cp.async.commit_group;" ::: "memory")
#define CPWAIT(n)   asm volatile("cp.async.wait_group %0;" :: "n"(n) : "memory")

#define LDSM4(r, a) asm volatile("ldmatrix.sync.aligned.m8n8.x4.shared.b16 {%0,%1,%2,%3}, [%4];" \
    : "=r"((r)[0]), "=r"((r)[1]), "=r"((r)[2]), "=r"((r)[3]) : "r"(a))

// c += a*b   (m16n8k16 fp16 in, fp32 accumulate)
#define MMAH(c, a, b0, b1) asm volatile( \
    "mma.sync.aligned.m16n8k16.row.col.f32.f16.f16.f32 " \
    "{%0,%1,%2,%3},{%4,%5,%6,%7},{%8,%9},{%0,%1,%2,%3};" \
    : "+f"((c)[0]), "+f"((c)[1]), "+f"((c)[2]), "+f"((c)[3]) \
    : "r"((a)[0]), "r"((a)[1]), "r"((a)[2]), "r"((a)[3]), "r"(b0), "r"(b1))

// ---------------- setup kernels ----------------
// One warp per token, float4 loads (Wg rows stay hot in L1/L2).
__global__ void k_router(const float* __restrict__ x,
                         const float* __restrict__ Wg,
                         const float* __restrict__ bg) {
    int warp = threadIdx.x >> 5, lane = threadIdx.x & 31;
    int t = blockIdx.x * 4 + warp;
    const float4* xr = reinterpret_cast<const float4*>(x + (size_t)t * DIM);
    const float4* wg = reinterpret_cast<const float4*>(Wg);
    float acc[NE];
#pragma unroll
    for (int e = 0; e < NE; e++) acc[e] = 0.f;
#pragma unroll
    for (int k = 0; k < 8; k++) {
        float4 xv = xr[lane + k * 32];
#pragma unroll
        for (int e = 0; e < NE; e++) {
            float4 w = wg[e * 256 + lane + k * 32];
            acc[e] += xv.x * w.x + xv.y * w.y + xv.z * w.z + xv.w * w.w;
        }
    }
#pragma unroll
    for (int e = 0; e < NE; e++)
#pragma unroll
        for (int o = 16; o > 0; o >>= 1)
            acc[e] += __shfl_xor_sync(0xffffffffu, acc[e], o);
    if (lane == 0) {
        float v0 = -1e30f, v1 = -1e30f; int i0 = 0, i1 = 0;
#pragma unroll
        for (int e = 0; e < NE; e++) {
            float v = acc[e] + bg[e];
            if (v > v0)      { v1 = v0; i1 = i0; v0 = v; i0 = e; }
            else if (v > v1) { v1 = v;  i1 = e; }
        }
        float e1 = __expf(v1 - v0);
        float w0 = 1.f / (1.f + e1);
        float w1 = e1 * w0;
        g_eid[2*t] = i0; g_eid[2*t+1] = i1;
        g_ew [2*t] = w0; g_ew [2*t+1] = w1;
    }
}

// histogram + offsets + fill reset, single block
__global__ void k_count() {
    __shared__ int cnt[NE];
    int tid = threadIdx.x;
    if (tid < NE) cnt[tid] = 0;
    __syncthreads();
    for (int i = tid; i < TOK * 2; i += 256) atomicAdd(&cnt[g_eid[i]], 1);
    __syncthreads();
    if (tid == 0) {
        int acc = 0;
        for (int e = 0; e < NE; e++) {
            g_off[e]  = acc;
            g_rows[e] = cnt[e];
            g_fill[e] = 0;
            acc += ((cnt[e] + BM - 1) / BM) * BM;
        }
    }
}

__global__ void k_scatter() {
    int t = blockIdx.x * blockDim.x + threadIdx.x;
    if (t >= TOK) return;
#pragma unroll
    for (int s = 0; s < 2; s++) {
        int e = g_eid[2*t + s];
        int pos = g_off[e] + atomicAdd(&g_fill[e], 1);
        g_perm[pos] = t;
        g_pw[pos]   = g_ew[2*t + s];
    }
}

// Gather tokens into per-expert buckets as fp16 (RN); zero the pad rows. MLP=2.
__global__ void k_gather(const float* __restrict__ x) {
    int pos = blockIdx.x;
    bool valid = false;
#pragma unroll
    for (int e = 0; e < NE; e++)
        valid |= (pos >= g_off[e] && pos < g_off[e] + g_rows[e]);
    int c = threadIdx.x;   // 0..127
    float4 v0 = make_float4(0.f,0.f,0.f,0.f), v1 = v0;
    if (valid) {
        int t = g_perm[pos];
        const float4* src = reinterpret_cast<const float4*>(x + (size_t)t * DIM);
        v0 = src[c];
        v1 = src[c + 128];
    }
    __half2* dst = reinterpret_cast<__half2*>(g_X + (size_t)pos * DIM);
    dst[2*c]           = __floats2half2_rn(v0.x, v0.y);
    dst[2*c + 1]       = __floats2half2_rn(v0.z, v0.w);
    dst[2*(c+128)]     = __floats2half2_rn(v1.x, v1.y);
    dst[2*(c+128) + 1] = __floats2half2_rn(v1.z, v1.w);
}

// fp32 -> fp16 conversion of one DFF-chunk of W1 and W3 (all experts).
__global__ void k_wconv13c(const float4* __restrict__ s1, const float4* __restrict__ s3,
                           __half2* __restrict__ d1, __half2* __restrict__ d3, int chunk) {
    int e = blockIdx.y;
    size_t base = ((size_t)e * DFFC + (size_t)chunk * (DFFC / NCHUNK)) * DIM / 4;
    size_t i = base + blockIdx.x * 256 + threadIdx.x;
    float4 v = s1[i];
    d1[2*i]   = __floats2half2_rn(v.x, v.y);
    d1[2*i+1] = __floats2half2_rn(v.z, v.w);
    float4 w = s3[i];
    d3[2*i]   = __floats2half2_rn(w.x, w.y);
    d3[2*i+1] = __floats2half2_rn(w.z, w.w);
}

__global__ void k_wconv(const float4* __restrict__ src, __half2* __restrict__ dst, int n4) {
    int i = blockIdx.x * blockDim.x + threadIdx.x;
    if (i >= n4) return;
    float4 v = src[i];
    dst[2*i]   = __floats2half2_rn(v.x, v.y);
    dst[2*i+1] = __floats2half2_rn(v.z, v.w);
}

__global__ void k_zero(float4* __restrict__ y) {
    y[blockIdx.x * 256 + threadIdx.x] = make_float4(0.f, 0.f, 0.f, 0.f);
}

__device__ __forceinline__ bool find_expert(int mt, int& e, int& m0, int& ne) {
    e = -1;
#pragma unroll
    for (int i = 0; i < NE; i++) {
        int o = g_off[i], r = g_rows[i];
        int t0 = o / BM, tl = (r + BM - 1) / BM;
        if (mt >= t0 && mt < t0 + tl) { e = i; m0 = o + (mt - t0) * BM; ne = o + r; }
    }
    return e >= 0;
}

// =============== GEMM 1+3 fused: H = silu(X@W1^T)*(X@W3^T), fp16 mma ===============
// CTA tile 128x64 (dual matrices), BK=32, 3-stage cp.async, 8 warps (2m x 4n).
// dyn smem halfs: A 3x(128*40) @0; B1 3x(64*40) @30720B; B3 @46080B. Total 61440B.
__global__ void __launch_bounds__(256, 2)
k_gemm13(int nbase) {
    extern __shared__ __half sm13[];
    const uint32_t sbu = smem_u32(sm13);

    int e, m0, ne_;
    if (!find_expert((int)blockIdx.x, e, m0, ne_)) return;

    const int tid = threadIdx.x, lane = tid & 31, wid = tid >> 5;
    const int wm = wid & 1, wn = wid >> 1;
    const int n0 = nbase + blockIdx.y * 64;

    const __half* Ah  = g_X  + (size_t)m0 * DIM;
    const __half* B1h = g_W1h + ((size_t)e * DFFC + n0) * DIM;
    const __half* B3h = g_W3h + ((size_t)e * DFFC + n0) * DIM;

#define G13_LOAD(s, k0) do {                                                    \
    _Pragma("unroll")                                                           \
    for (int l = 0; l < 2; l++) {                                               \
        int idx = tid + l * 256, row = idx >> 2, q = idx & 3;                   \
        CPA(sbu + (uint32_t)((s)*10240 + row*80 + q*16),                        \
            Ah + (size_t)row * DIM + (k0) + q * 8);                             \
    }                                                                           \
    { int row = tid >> 2, q = tid & 3;                                          \
      CPA(sbu + (uint32_t)(30720 + (s)*5120 + row*80 + q*16),                   \
          B1h + (size_t)row * DIM + (k0) + q * 8);                              \
      CPA(sbu + (uint32_t)(46080 + (s)*5120 + row*80 + q*16),                   \
          B3h + (size_t)row * DIM + (k0) + q * 8); }                            \
    CPCOMMIT();                                                                 \
} while (0)

    const uint32_t aBase = sbu +
        (uint32_t)(((wm*64 + (lane & 15)) * HSTR + (lane >> 4) * 8) * 2);
    const uint32_t bRow = (uint32_t)(wn*16 + (lane & 7) + ((lane >> 4) & 1) * 8);
    const uint32_t bCol = (uint32_t)(((lane >> 3) & 1) * 8);
    const uint32_t b1Base = sbu + 30720u + (bRow * HSTR + bCol) * 2;
    const uint32_t b3Base = b1Base + 15360u;

    float c1[4][2][4], c3[4][2][4];
#pragma unroll
    for (int i = 0; i < 4; i++)
#pragma unroll
        for (int j = 0; j < 2; j++)
#pragma unroll
            for (int q = 0; q < 4; q++) { c1[i][j][q] = 0.f; c3[i][j][q] = 0.f; }

    const int NS = DIM / BK;   // 32
    G13_LOAD(0, 0);
    G13_LOAD(1, BK);

    for (int i = 0; i < NS; i++) {
        int s = i % 3;
        if (i + 1 < NS) CPWAIT(1); else CPWAIT(0);
        __syncthreads();
        if (i + 2 < NS) G13_LOAD((i + 2) % 3, (i + 2) * BK);

        uint32_t b1f[2][4], b3f[2][4];
#pragma unroll
        for (int ks = 0; ks < 2; ks++) {
            LDSM4(b1f[ks], b1Base + (uint32_t)(s*5120 + ks*32));
            LDSM4(b3f[ks], b3Base + (uint32_t)(s*5120 + ks*32));
        }
#pragma unroll
        for (int ks = 0; ks < 2; ks++) {
#pragma unroll
            for (int mt = 0; mt < 4; mt++) {
                uint32_t a[4];
                LDSM4(a, aBase + (uint32_t)(s*10240 + mt*1280 + ks*32));
                MMAH(c1[mt][0], a, b1f[ks][0], b1f[ks][1]);
                MMAH(c1[mt][1], a, b1f[ks][2], b1f[ks][3]);
                MMAH(c3[mt][0], a, b3f[ks][0], b3f[ks][1]);
                MMAH(c3[mt][1], a, b3f[ks][2], b3f[ks][3]);
            }
        }
    }

    // epilogue: h = silu(c1) * c3 -> fp16 -> g_H (pad rows compute exact 0)
#pragma unroll
    for (int mt = 0; mt < 4; mt++)
#pragma unroll
        for (int nj = 0; nj < 2; nj++) {
            int row = m0 + wm*64 + mt*16 + (lane >> 2);
            int col = n0 + wn*16 + nj*8 + (lane & 3) * 2;
#pragma unroll
            for (int h = 0; h < 2; h++) {
                int r = row + h * 8;
                float z0 = c1[mt][nj][h*2],   g0 = z0 / (1.f + __expf(-z0)) * c3[mt][nj][h*2];
                float z1 = c1[mt][nj][h*2+1], g1 = z1 / (1.f + __expf(-z1)) * c3[mt][nj][h*2+1];
                *reinterpret_cast<__half2*>(g_H + (size_t)r * DFFC + col) =
                    __floats2half2_rn(g0, g1);
            }
        }
}

// =============== GEMM 2: y += w * (H @ W2^T), fp16 mma ===============
// CTA tile 128x128, BK=32, 3-stage, 8 warps (2m x 4n), warp tile 64x32.
// dyn smem halfs: A 3x(128*40) @0; B 3x(128*40) @30720B. Total 61440B.
__global__ void __launch_bounds__(256, 2)
k_gemm2(float* __restrict__ y) {
    extern __shared__ __half sm2[];
    const uint32_t sbu = smem_u32(sm2);
    __shared__ int   srow[BM];
    __shared__ float swt[BM];

    int e, m0, ne_;
    if (!find_expert((int)blockIdx.y, e, m0, ne_)) return;

    const int tid = threadIdx.x, lane = tid & 31, wid = tid >> 5;
    const int wm = wid & 1, wn = wid >> 1;
    const int n0 = blockIdx.x * 128;

    if (tid < BM) {
        int pos = m0 + tid;
        bool v = pos < ne_;
        srow[tid] = v ? g_perm[pos] : -1;
        swt[tid]  = v ? g_pw[pos]   : 0.f;
    }

    const __half* Ah = g_H + (size_t)m0 * DFFC;
    const __half* Bh = g_W2h + ((size_t)e * DIM + n0) * DFFC;

#define G2_LOAD(s, k0) do {                                                     \
    _Pragma("unroll")                                                           \
    for (int l = 0; l < 2; l++) {                                               \
        int idx = tid + l * 256, row = idx >> 2, q = idx & 3;                   \
        CPA(sbu + (uint32_t)((s)*10240 + row*80 + q*16),                        \
            Ah + (size_t)row * DFFC + (k0) + q * 8);                            \
        CPA(sbu + (uint32_t)(30720 + (s)*10240 + row*80 + q*16),                \
            Bh + (size_t)row * DFFC + (k0) + q * 8);                            \
    }                                                                           \
    CPCOMMIT();                                                                 \
} while (0)

    const uint32_t aBase = sbu +
        (uint32_t)(((wm*64 + (lane & 15)) * HSTR + (lane >> 4) * 8) * 2);
    const uint32_t bRow = (uint32_t)(wn*32 + (lane & 7) + ((lane >> 4) & 1) * 8);
    const uint32_t bCol = (uint32_t)(((lane >> 3) & 1) * 8);
    const uint32_t bBase = sbu + 30720u + (bRow * HSTR + bCol) * 2;

    float c[4][4][4];
#pragma unroll
    for (int i = 0; i < 4; i++)
#pragma unroll
        for (int j = 0; j < 4; j++)
#pragma unroll
            for (int q = 0; q < 4; q++) c[i][j][q] = 0.f;

    const int NS = DFFC / BK;   // 128
    G2_LOAD(0, 0);
    G2_LOAD(1, BK);

    for (int i = 0; i < NS; i++) {
        int s = i % 3;
        if (i + 1 < NS) CPWAIT(1); else CPWAIT(0);
        __syncthreads();
        if (i + 2 < NS) G2_LOAD((i + 2) % 3, (i + 2) * BK);

        uint32_t bf[2][2][4];   // [nt][ks]
#pragma unroll
        for (int nt = 0; nt < 2; nt++)
#pragma unroll
            for (int ks = 0; ks < 2; ks++)
                LDSM4(bf[nt][ks], bBase + (uint32_t)(s*10240 + nt*1280 + ks*32));
#pragma unroll
        for (int ks = 0; ks < 2; ks++) {
#pragma unroll
            for (int mt = 0; mt < 4; mt++) {
                uint32_t a[4];
                LDSM4(a, aBase + (uint32_t)(s*10240 + mt*1280 + ks*32));
#pragma unroll
                for (int nt = 0; nt < 2; nt++) {
                    MMAH(c[mt][nt*2],   a, bf[nt][ks][0], bf[nt][ks][1]);
                    MMAH(c[mt][nt*2+1], a, bf[nt][ks][2], bf[nt][ks][3]);
                }
            }
        }
    }

    // epilogue: weighted scatter-add (2 commutative fp32 adds per output element)
#pragma unroll
    for (int mt = 0; mt < 4; mt++) {
        int rl = wm*64 + mt*16 + (lane >> 2);
#pragma unroll
        for (int h = 0; h < 2; h++) {
            int r = rl + h * 8;
            int t = srow[r];
            if (t >= 0) {
                float w = swt[r];
                float* yr = y + (size_t)t * DIM + n0 + wn*32 + (lane & 3) * 2;
#pragma unroll
                for (int nj = 0; nj < 4; nj++) {
                    atomicAdd(&yr[nj*8],     w * c[mt][nj][h*2]);
                    atomicAdd(&yr[nj*8 + 1], w * c[mt][nj][h*2+1]);
                }
            }
        }
    }
}

// ---------------- launch ----------------
#define SMEM_GEMM 61440

extern "C" void kernel_launch(void* const* d_in, const int* in_sizes, int n_in,
                              void* d_out, int out_size) {
    const float* x  = (const float*)d_in[0];
    const float* Wg = (const float*)d_in[1];
    const float* bg = (const float*)d_in[2];
    const float* W1 = (const float*)d_in[3];
    const float* W2 = (const float*)d_in[4];
    const float* W3 = (const float*)d_in[5];
    float* y = (float*)d_out;

    // One-time infra: exactly ONE extra stream + 4 tiny events (same footprint
    // as the passing R7/R10 runs). First call is the non-captured correctness run.
    static cudaStream_t s2 = nullptr;
    static cudaEvent_t evFork, evC0, evGather, evG1;
    if (s2 == nullptr) {
        cudaStreamCreateWithFlags(&s2, cudaStreamNonBlocking);
        cudaEventCreateWithFlags(&evFork,   cudaEventDisableTiming);
        cudaEventCreateWithFlags(&evC0,     cudaEventDisableTiming);
        cudaEventCreateWithFlags(&evGather, cudaEventDisableTiming);
        cudaEventCreateWithFlags(&evG1,     cudaEventDisableTiming);
        cudaFuncSetAttribute(k_gemm13, cudaFuncAttributeMaxDynamicSharedMemorySize, SMEM_GEMM);
        cudaFuncSetAttribute(k_gemm2,  cudaFuncAttributeMaxDynamicSharedMemorySize, SMEM_GEMM);
    }

    __half* w1h; cudaGetSymbolAddress((void**)&w1h, g_W1h);
    __half* w3h; cudaGetSymbolAddress((void**)&w3h, g_W3h);
    __half* w2h; cudaGetSymbolAddress((void**)&w2h, g_W2h);
    const int NW = NE * DFFC * DIM / 4;   // float4 count per weight tensor

    // Side stream s2: W1/W3 chunk conversions, then gemm13 chunk 1 as soon as
    // its weights + gather are ready (no W2conv/zero in front of it anymore).
    cudaEventRecord(evFork, 0);
    cudaStreamWaitEvent(s2, evFork, 0);
    dim3 gwc((DFFC / NCHUNK) * DIM / 4 / 256, NE);   // (2048, 8)
    k_wconv13c<<<gwc, 256, 0, s2>>>((const float4*)W1, (const float4*)W3,
                                    (__half2*)w1h, (__half2*)w3h, 0);
    cudaEventRecord(evC0, s2);
    k_wconv13c<<<gwc, 256, 0, s2>>>((const float4*)W1, (const float4*)W3,
                                    (__half2*)w1h, (__half2*)w3h, 1);

    // Main stream: routing chain (overlaps with chunk-0 weight conversion).
    k_router<<<TOK / 4, 128>>>(x, Wg, bg);
    k_count<<<1, 256>>>();
    k_scatter<<<TOK / 256, 256>>>();
    k_gather<<<CAP, 128>>>(x);
    cudaEventRecord(evGather, 0);

    dim3 g13(MT, (DFFC / NCHUNK) / 64);   // (72, 32)
    // gemm13 chunk 1 on s2: weights ready by s2 program order; needs gather.
    cudaStreamWaitEvent(s2, evGather, 0);
    k_gemm13<<<g13, 256, SMEM_GEMM, s2>>>(DFFC / NCHUNK);
    cudaEventRecord(evG1, s2);

    // gemm13 chunk 0 on main: gated by gather (program order) + its weights.
    cudaStreamWaitEvent(0, evC0, 0);
    k_gemm13<<<g13, 256, SMEM_GEMM>>>(0);

    // W2 conversion + y zeroing on main AFTER gemm13-c0: they drain into
    // gemm13-c1's solo window, off the critical path.
    k_wconv<<<(NW + 255) / 256, 256>>>((const float4*)W2, (__half2*)w2h, NW);
    k_zero<<<(TOK * DIM) / 1024, 256>>>((float4*)y);

    // gemm2 on main: program order covers c0 + W2h + zeroed y; evG1 covers c1.
    cudaStreamWaitEvent(0, evG1, 0);
    dim3 g2(DIM / 128, MT);            // x = n (8): g_H tile L2 reuse
    k_gemm2<<<g2, 256, SMEM_GEMM>>>(y);
}